// round 1
// baseline (speedup 1.0000x reference)
#include <cuda_runtime.h>
#include <cstdint>

// ---------------------------------------------------------------------------
// MetaGIN fused kernel, fp32 SIMT with f32x2 packed FMA (FFMA2).
//   K1: xs = x@W_src^T, xt = x@W_tgt^T  -> __device__ scratch
//   K2: per-64-edge tile: gather+bag+groupnorm -> gate/val -> W_post GEMM
//       -> red.global.add.v4.f32 scatter into d_out
//   K3: out *= deg^deg_param
// ---------------------------------------------------------------------------

#define WDIM 256

__device__ float g_xs[2560000];   // [N,256] scratch (N=10000)
__device__ float g_xt[2560000];

typedef unsigned long long u64;

__device__ __forceinline__ void lds_v2u64(u64 &lo, u64 &hi, unsigned addr) {
    asm volatile("ld.shared.v2.u64 {%0,%1}, [%2];" : "=l"(lo), "=l"(hi) : "r"(addr));
}
__device__ __forceinline__ u64 ffma2(u64 a, u64 b, u64 c) {
    u64 d;
    asm("fma.rn.f32x2 %0, %1, %2, %3;" : "=l"(d) : "l"(a), "l"(b), "l"(c));
    return d;
}
__device__ __forceinline__ float unpack_sum(u64 p) {
    unsigned lo, hi;
    asm("mov.b64 {%0,%1}, %2;" : "=r"(lo), "=r"(hi) : "l"(p));
    return __uint_as_float(lo) + __uint_as_float(hi);
}

// ---------------------------------------------------------------------------
// K1: node GEMM. Block = 64 nodes x 256 outputs. blockIdx.y selects W_src/W_tgt.
// smem: x tile 64 rows x 260 floats (16640 f) + W tile 256x32 swizzled (8192 f)
// ---------------------------------------------------------------------------
extern "C" __global__ void __launch_bounds__(512, 1)
node_gemm_kernel(const float* __restrict__ x,
                 const float* __restrict__ Wsrc,
                 const float* __restrict__ Wtgt, int N)
{
    extern __shared__ float sm[];
    float4* a4 = reinterpret_cast<float4*>(sm);            // 64*65 f4
    float4* w4 = reinterpret_cast<float4*>(sm + 16640);    // 2048 f4
    const float* Wm = blockIdx.y ? Wtgt : Wsrc;
    float* og = blockIdx.y ? g_xt : g_xs;

    const int t  = threadIdx.x;
    const int nb = blockIdx.x * 64;

    // stage x tile (coalesced; rows padded to 65 float4)
#pragma unroll
    for (int r = 0; r < 8; r++) {
        int id = t + 512 * r;
        int row = id >> 6, c4 = id & 63;
        int n = nb + row;
        float4 v = make_float4(0.f, 0.f, 0.f, 0.f);
        if (n < N) v = __ldg(reinterpret_cast<const float4*>(x + (size_t)n * WDIM) + c4);
        a4[row * 65 + c4] = v;
    }

    const int et = t >> 5, jt = t & 31;
    unsigned sa = (unsigned)__cvta_generic_to_shared(sm);
    unsigned sw = sa + 16640u * 4u;

    u64 accp[4][8];
#pragma unroll
    for (int ee = 0; ee < 4; ee++)
#pragma unroll
        for (int jj = 0; jj < 8; jj++) accp[ee][jj] = 0ull;

#pragma unroll 1
    for (int kt = 0; kt < 8; kt++) {
        __syncthreads();
#pragma unroll
        for (int r = 0; r < 4; r++) {
            int id = t + 512 * r;
            int j = id >> 3, kq = id & 7;
            w4[j * 8 + (kq ^ ((j >> 3) & 7))] =
                __ldg(reinterpret_cast<const float4*>(Wm + (size_t)j * WDIM + kt * 32) + kq);
        }
        __syncthreads();
#pragma unroll
        for (int kq = 0; kq < 8; kq++) {
            u64 aL[4], aH[4];
#pragma unroll
            for (int ee = 0; ee < 4; ee++)
                lds_v2u64(aL[ee], aH[ee],
                          sa + (unsigned)(((et * 4 + ee) * 65 + kt * 8 + kq) * 16));
#pragma unroll
            for (int half = 0; half < 2; half++) {
                u64 bL[4], bH[4];
#pragma unroll
                for (int jj = 0; jj < 4; jj++)
                    lds_v2u64(bL[jj], bH[jj],
                              sw + (unsigned)(((jt * 8 + half * 4 + jj) * 8 + (kq ^ (jt & 7))) * 16));
#pragma unroll
                for (int ee = 0; ee < 4; ee++)
#pragma unroll
                    for (int jj = 0; jj < 4; jj++)
                        accp[ee][half * 4 + jj] =
                            ffma2(aH[ee], bH[jj], ffma2(aL[ee], bL[jj], accp[ee][half * 4 + jj]));
            }
        }
    }

#pragma unroll
    for (int ee = 0; ee < 4; ee++) {
        int n = nb + et * 4 + ee;
        if (n >= N) continue;
        float r0 = unpack_sum(accp[ee][0]), r1 = unpack_sum(accp[ee][1]);
        float r2 = unpack_sum(accp[ee][2]), r3 = unpack_sum(accp[ee][3]);
        float r4 = unpack_sum(accp[ee][4]), r5 = unpack_sum(accp[ee][5]);
        float r6 = unpack_sum(accp[ee][6]), r7 = unpack_sum(accp[ee][7]);
        float4* py = reinterpret_cast<float4*>(og + (size_t)n * WDIM + jt * 8);
        py[0] = make_float4(r0, r1, r2, r3);
        py[1] = make_float4(r4, r5, r6, r7);
    }
}

// ---------------------------------------------------------------------------
// K2: fused edge kernel. Block = 64 edges, 512 threads.
// smem floats: xn[16640] | gin[16640] | ws[8192] | tgt[64 ints]
// ---------------------------------------------------------------------------
extern "C" __global__ void __launch_bounds__(512, 1)
edge_kernel(const int* __restrict__ eidx, const int* __restrict__ eattr,
            const float* __restrict__ emb, const float* __restrict__ Wg,
            const float* __restrict__ Wv,  const float* __restrict__ Wp,
            float* __restrict__ out, int E)
{
    extern __shared__ float sm[];
    float4* xn4  = reinterpret_cast<float4*>(sm);            // 64 x 65 f4
    float4* gin4 = reinterpret_cast<float4*>(sm + 16640);
    float4* w4   = reinterpret_cast<float4*>(sm + 33280);    // 2048 f4
    int* tgt_s   = reinterpret_cast<int*>(sm + 41472);

    const int t  = threadIdx.x;
    const int eb = blockIdx.x * 64;

    // ---- Phase 1: gather xx, embedding bag, groupnorm -> xn, gin (smem) ----
    {
        const int el = t >> 3, j = t & 7;     // 8 threads/edge, one head each
        const int e = eb + el;
        const int base4 = el * 65 + j * 8;
        if (e < E) {
            int s  = __ldg(eidx + e);
            int tg = __ldg(eidx + E + e);
            if (j == 0) tgt_s[el] = tg;
            const float4* ps = reinterpret_cast<const float4*>(g_xs + (size_t)s  * WDIM + j * 32);
            const float4* pt = reinterpret_cast<const float4*>(g_xt + (size_t)tg * WDIM + j * 32);
            float4 xx[8];
            float sum = 0.f, sq = 0.f;
#pragma unroll
            for (int q = 0; q < 8; q++) {
                float4 a = ps[q], b = pt[q];
                float4 v = make_float4(a.x + b.x, a.y + b.y, a.z + b.z, a.w + b.w);
                xx[q] = v;
                sum += v.x + v.y + v.z + v.w;
                sq  += v.x * v.x + v.y * v.y + v.z * v.z + v.w * v.w;
            }
            float mu   = sum * (1.f / 32.f);
            float var  = sq * (1.f / 32.f) - mu * mu;
            float rstd = rsqrtf(var + 1e-5f);

            float4 bg[8];
#pragma unroll
            for (int q = 0; q < 8; q++) bg[q] = make_float4(0.f, 0.f, 0.f, 0.f);
            float cnt = 0.f;
#pragma unroll
            for (int b = 0; b < 3; b++) {
                int a = __ldg(eattr + (size_t)e * 3 + b);
                if (a != 0) {
                    cnt += 1.f;
                    const float4* pe = reinterpret_cast<const float4*>(emb + (size_t)a * WDIM + j * 32);
#pragma unroll
                    for (int q = 0; q < 8; q++) {
                        float4 ev = __ldg(pe + q);
                        bg[q].x += ev.x; bg[q].y += ev.y; bg[q].z += ev.z; bg[q].w += ev.w;
                    }
                }
            }
            float inv = 1.f / fmaxf(cnt, 1.f);
#pragma unroll
            for (int q = 0; q < 8; q++) {
                float4 xv, gv;
                xv.x = (xx[q].x - mu) * rstd;  xv.y = (xx[q].y - mu) * rstd;
                xv.z = (xx[q].z - mu) * rstd;  xv.w = (xx[q].w - mu) * rstd;
                gv.x = xv.x + bg[q].x * inv;   gv.y = xv.y + bg[q].y * inv;
                gv.z = xv.z + bg[q].z * inv;   gv.w = xv.w + bg[q].w * inv;
                xn4[base4 + q]  = xv;
                gin4[base4 + q] = gv;
            }
        } else {
            if (j == 0) tgt_s[el] = -1;
            float4 z = make_float4(0.f, 0.f, 0.f, 0.f);
#pragma unroll
            for (int q = 0; q < 8; q++) { xn4[base4 + q] = z; gin4[base4 + q] = z; }
        }
    }
    __syncthreads();

    // ---- Phase 2: act = relu(gin.Wg) * (xn.Wv), in-place into xn buffer ----
    {
        const int w = t >> 5, lane = t & 31;
        const int h = w & 7, eg = w >> 3;    // warp = (head, 32-edge group)
        u64 wgp[16], wvp[16];
        const ulonglong2* pg = reinterpret_cast<const ulonglong2*>(Wg + (size_t)(h * 32 + lane) * 32);
        const ulonglong2* pv = reinterpret_cast<const ulonglong2*>(Wv + (size_t)(h * 32 + lane) * 32);
#pragma unroll
        for (int q = 0; q < 8; q++) {
            ulonglong2 ug = __ldg(pg + q); wgp[2 * q] = ug.x; wgp[2 * q + 1] = ug.y;
            ulonglong2 uv = __ldg(pv + q); wvp[2 * q] = uv.x; wvp[2 * q + 1] = uv.y;
        }
        unsigned sxn  = (unsigned)__cvta_generic_to_shared(sm);
        unsigned sgin = sxn + 16640u * 4u;
#pragma unroll 2
        for (int i = 0; i < 32; i++) {
            int el = eg * 32 + i;
            unsigned bx = sxn  + (unsigned)((el * 65 + h * 8) * 16);
            unsigned bb = sgin + (unsigned)((el * 65 + h * 8) * 16);
            u64 ga = 0ull, va = 0ull;
#pragma unroll
            for (int q = 0; q < 8; q++) {
                u64 xl, xh, gl, gh;
                lds_v2u64(gl, gh, bb + q * 16);
                lds_v2u64(xl, xh, bx + q * 16);
                ga = ffma2(gh, wgp[2 * q + 1], ffma2(gl, wgp[2 * q], ga));
                va = ffma2(xh, wvp[2 * q + 1], ffma2(xl, wvp[2 * q], va));
            }
            float gv = unpack_sum(ga);
            float vv = unpack_sum(va);
            // exclusive (e,h) slice per warp: safe in-place overwrite of xn
            sm[el * 260 + h * 32 + lane] = fmaxf(gv, 0.f) * vv;
        }
    }
    __syncthreads();

    // ---- Phase 3: out_e = act @ Wp^T  (64x256x256), then vector red scatter --
    const int et = t >> 5, jt = t & 31;
    unsigned sa = (unsigned)__cvta_generic_to_shared(sm);
    unsigned sw = sa + 33280u * 4u;
    u64 accp[4][8];
#pragma unroll
    for (int ee = 0; ee < 4; ee++)
#pragma unroll
        for (int jj = 0; jj < 8; jj++) accp[ee][jj] = 0ull;

#pragma unroll 1
    for (int kt = 0; kt < 8; kt++) {
        __syncthreads();
#pragma unroll
        for (int r = 0; r < 4; r++) {
            int id = t + 512 * r;
            int j = id >> 3, kq = id & 7;
            w4[j * 8 + (kq ^ ((j >> 3) & 7))] =
                __ldg(reinterpret_cast<const float4*>(Wp + (size_t)j * WDIM + kt * 32) + kq);
        }
        __syncthreads();
#pragma unroll
        for (int kq = 0; kq < 8; kq++) {
            u64 aL[4], aH[4];
#pragma unroll
            for (int ee = 0; ee < 4; ee++)
                lds_v2u64(aL[ee], aH[ee],
                          sa + (unsigned)(((et * 4 + ee) * 65 + kt * 8 + kq) * 16));
#pragma unroll
            for (int half = 0; half < 2; half++) {
                u64 bL[4], bH[4];
#pragma unroll
                for (int jj = 0; jj < 4; jj++)
                    lds_v2u64(bL[jj], bH[jj],
                              sw + (unsigned)(((jt * 8 + half * 4 + jj) * 8 + (kq ^ (jt & 7))) * 16));
#pragma unroll
                for (int ee = 0; ee < 4; ee++)
#pragma unroll
                    for (int jj = 0; jj < 4; jj++)
                        accp[ee][half * 4 + jj] =
                            ffma2(aH[ee], bH[jj], ffma2(aL[ee], bL[jj], accp[ee][half * 4 + jj]));
            }
        }
    }

#pragma unroll
    for (int ee = 0; ee < 4; ee++) {
        int el = et * 4 + ee;
        int tg = tgt_s[el];
        if (tg < 0) continue;
        float r0 = unpack_sum(accp[ee][0]), r1 = unpack_sum(accp[ee][1]);
        float r2 = unpack_sum(accp[ee][2]), r3 = unpack_sum(accp[ee][3]);
        float r4 = unpack_sum(accp[ee][4]), r5 = unpack_sum(accp[ee][5]);
        float r6 = unpack_sum(accp[ee][6]), r7 = unpack_sum(accp[ee][7]);
        float* po = out + (size_t)tg * WDIM + jt * 8;
        asm volatile("red.global.add.v4.f32 [%0], {%1,%2,%3,%4};"
                     :: "l"(po), "f"(r0), "f"(r1), "f"(r2), "f"(r3) : "memory");
        asm volatile("red.global.add.v4.f32 [%0], {%1,%2,%3,%4};"
                     :: "l"(po + 4), "f"(r4), "f"(r5), "f"(r6), "f"(r7) : "memory");
    }
}

// ---------------------------------------------------------------------------
// K3: out[n,j] *= deg[n]^deg_param[j]
// ---------------------------------------------------------------------------
extern "C" __global__ void scale_kernel(float* __restrict__ out,
                                        const float* __restrict__ deg,
                                        const float* __restrict__ dp, int N)
{
    int idx = blockIdx.x * blockDim.x + threadIdx.x;
    if (idx < N * WDIM) {
        int n = idx >> 8, j = idx & 255;
        out[idx] *= __powf(__ldg(deg + n), __ldg(dp + j));
    }
}

// ---------------------------------------------------------------------------
extern "C" void kernel_launch(void* const* d_in, const int* in_sizes, int n_in,
                              void* d_out, int out_size)
{
    const float* x    = (const float*)d_in[0];
    const float* deg  = (const float*)d_in[1];
    const int*   eidx = (const int*)d_in[2];
    const int*   eattr= (const int*)d_in[3];
    const float* Wsrc = (const float*)d_in[4];
    const float* Wtgt = (const float*)d_in[5];
    const float* emb  = (const float*)d_in[6];
    const float* Wg   = (const float*)d_in[7];
    const float* Wv   = (const float*)d_in[8];
    const float* Wp   = (const float*)d_in[9];
    const float* dp   = (const float*)d_in[10];
    float* out = (float*)d_out;

    int N = in_sizes[0] / WDIM;
    int E = in_sizes[2] / 2;

    const int NODE_SMEM = (16640 + 8192) * 4;                // 99328 B
    const int EDGE_SMEM = (16640 * 2 + 8192) * 4 + 64 * 4;   // 166400 B

    cudaFuncSetAttribute(node_gemm_kernel,
                         cudaFuncAttributeMaxDynamicSharedMemorySize, NODE_SMEM);
    cudaFuncSetAttribute(edge_kernel,
                         cudaFuncAttributeMaxDynamicSharedMemorySize, EDGE_SMEM);

    cudaMemsetAsync(d_out, 0, (size_t)N * WDIM * sizeof(float));

    dim3 ng((N + 63) / 64, 2);
    node_gemm_kernel<<<ng, 512, NODE_SMEM>>>(x, Wsrc, Wtgt, N);
    edge_kernel<<<(E + 63) / 64, 512, EDGE_SMEM>>>(eidx, eattr, emb, Wg, Wv, Wp, out, E);
    scale_kernel<<<((size_t)N * WDIM + 511) / 512, 512>>>(out, deg, dp, N);
}

// round 3
// speedup vs baseline: 1.4072x; 1.4072x over previous
#include <cuda_runtime.h>
#include <cuda_bf16.h>
#include <cstdint>

#define WDIM 256

// ---------------------------------------------------------------------------
// Scratch (device globals: allocation-free per harness rules)
// ---------------------------------------------------------------------------
__device__ float g_xs[2560000];            // [N,256]
__device__ float g_xt[2560000];
__device__ unsigned short g_act_hi[81920000];   // [E,256] bf16 hi
__device__ unsigned short g_act_lo[81920000];   // [E,256] bf16 lo
__device__ unsigned short g_wp_hi[65536];       // W_post bf16 hi (row n, col k)
__device__ unsigned short g_wp_lo[65536];

typedef unsigned long long u64;

__device__ __forceinline__ void lds_v2u64(u64 &lo, u64 &hi, unsigned addr) {
    asm volatile("ld.shared.v2.u64 {%0,%1}, [%2];" : "=l"(lo), "=l"(hi) : "r"(addr));
}
__device__ __forceinline__ u64 ffma2(u64 a, u64 b, u64 c) {
    u64 d;
    asm("fma.rn.f32x2 %0, %1, %2, %3;" : "=l"(d) : "l"(a), "l"(b), "l"(c));
    return d;
}
__device__ __forceinline__ float unpack_sum(u64 p) {
    unsigned lo, hi;
    asm("mov.b64 {%0,%1}, %2;" : "=r"(lo), "=r"(hi) : "l"(p));
    return __uint_as_float(lo) + __uint_as_float(hi);
}
__device__ __forceinline__ unsigned sw128(unsigned x) { return x ^ ((x >> 3) & 0x70u); }
__device__ __forceinline__ void cpa16(unsigned dst, const void* src) {
    asm volatile("cp.async.cg.shared.global [%0], [%1], 16;" :: "r"(dst), "l"(src));
}
__device__ __forceinline__ void zfill16(unsigned dst) {
    asm volatile("st.shared.v4.b32 [%0], {%1,%1,%1,%1};" :: "r"(dst), "r"(0u));
}
__device__ __forceinline__ void ldm_x4(unsigned &r0, unsigned &r1, unsigned &r2,
                                       unsigned &r3, unsigned addr) {
    asm volatile("ldmatrix.sync.aligned.m8n8.x4.shared.b16 {%0,%1,%2,%3}, [%4];"
                 : "=r"(r0), "=r"(r1), "=r"(r2), "=r"(r3) : "r"(addr));
}
__device__ __forceinline__ void mma16816(float* d, const unsigned* a,
                                         unsigned b0, unsigned b1) {
    asm volatile(
        "mma.sync.aligned.m16n8k16.row.col.f32.bf16.bf16.f32 "
        "{%0,%1,%2,%3}, {%4,%5,%6,%7}, {%8,%9}, {%0,%1,%2,%3};"
        : "+f"(d[0]), "+f"(d[1]), "+f"(d[2]), "+f"(d[3])
        : "r"(a[0]), "r"(a[1]), "r"(a[2]), "r"(a[3]), "r"(b0), "r"(b1));
}

// ---------------------------------------------------------------------------
// K1: node GEMM (fp32 FFMA2). Block = 64 nodes x 256 outs; y selects src/tgt.
// ---------------------------------------------------------------------------
extern "C" __global__ void __launch_bounds__(512, 1)
node_gemm_kernel(const float* __restrict__ x,
                 const float* __restrict__ Wsrc,
                 const float* __restrict__ Wtgt, int N)
{
    extern __shared__ float sm[];
    float4* a4 = reinterpret_cast<float4*>(sm);
    float4* w4 = reinterpret_cast<float4*>(sm + 16640);
    const float* Wm = blockIdx.y ? Wtgt : Wsrc;
    float* og = blockIdx.y ? g_xt : g_xs;

    const int t  = threadIdx.x;
    const int nb = blockIdx.x * 64;

#pragma unroll
    for (int r = 0; r < 8; r++) {
        int id = t + 512 * r;
        int row = id >> 6, c4 = id & 63;
        int n = nb + row;
        float4 v = make_float4(0.f, 0.f, 0.f, 0.f);
        if (n < N) v = __ldg(reinterpret_cast<const float4*>(x + (size_t)n * WDIM) + c4);
        a4[row * 65 + c4] = v;
    }

    const int et = t >> 5, jt = t & 31;
    unsigned sa = (unsigned)__cvta_generic_to_shared(sm);
    unsigned sw = sa + 16640u * 4u;

    u64 accp[4][8];
#pragma unroll
    for (int ee = 0; ee < 4; ee++)
#pragma unroll
        for (int jj = 0; jj < 8; jj++) accp[ee][jj] = 0ull;

#pragma unroll 1
    for (int kt = 0; kt < 8; kt++) {
        __syncthreads();
#pragma unroll
        for (int r = 0; r < 4; r++) {
            int id = t + 512 * r;
            int j = id >> 3, kq = id & 7;
            w4[j * 8 + (kq ^ ((j >> 3) & 7))] =
                __ldg(reinterpret_cast<const float4*>(Wm + (size_t)j * WDIM + kt * 32) + kq);
        }
        __syncthreads();
#pragma unroll
        for (int kq = 0; kq < 8; kq++) {
            u64 aL[4], aH[4];
#pragma unroll
            for (int ee = 0; ee < 4; ee++)
                lds_v2u64(aL[ee], aH[ee],
                          sa + (unsigned)(((et * 4 + ee) * 65 + kt * 8 + kq) * 16));
#pragma unroll
            for (int half = 0; half < 2; half++) {
                u64 bL[4], bH[4];
#pragma unroll
                for (int jj = 0; jj < 4; jj++)
                    lds_v2u64(bL[jj], bH[jj],
                              sw + (unsigned)(((jt * 8 + half * 4 + jj) * 8 + (kq ^ (jt & 7))) * 16));
#pragma unroll
                for (int ee = 0; ee < 4; ee++)
#pragma unroll
                    for (int jj = 0; jj < 4; jj++)
                        accp[ee][half * 4 + jj] =
                            ffma2(aH[ee], bH[jj], ffma2(aL[ee], bL[jj], accp[ee][half * 4 + jj]));
            }
        }
    }

#pragma unroll
    for (int ee = 0; ee < 4; ee++) {
        int n = nb + et * 4 + ee;
        if (n >= N) continue;
        float r0 = unpack_sum(accp[ee][0]), r1 = unpack_sum(accp[ee][1]);
        float r2 = unpack_sum(accp[ee][2]), r3 = unpack_sum(accp[ee][3]);
        float r4 = unpack_sum(accp[ee][4]), r5 = unpack_sum(accp[ee][5]);
        float r6 = unpack_sum(accp[ee][6]), r7 = unpack_sum(accp[ee][7]);
        float4* py = reinterpret_cast<float4*>(og + (size_t)n * WDIM + jt * 8);
        py[0] = make_float4(r0, r1, r2, r3);
        py[1] = make_float4(r4, r5, r6, r7);
    }
}

// ---------------------------------------------------------------------------
// W_post bf16 hi/lo split
// ---------------------------------------------------------------------------
extern "C" __global__ void wsplit_kernel(const float* __restrict__ Wp)
{
    int i = blockIdx.x * blockDim.x + threadIdx.x;
    if (i < 65536) {
        float v = Wp[i];
        __nv_bfloat16 h = __float2bfloat16(v);
        float lof = v - __bfloat162float(h);
        __nv_bfloat16 l = __float2bfloat16(lof);
        g_wp_hi[i] = *reinterpret_cast<unsigned short*>(&h);
        g_wp_lo[i] = *reinterpret_cast<unsigned short*>(&l);
    }
}

// ---------------------------------------------------------------------------
// K2: edge assembly -> act bf16 hi/lo. Block = 64 edges, 512 threads.
// ---------------------------------------------------------------------------
extern "C" __global__ void __launch_bounds__(512, 1)
assembly_kernel(const int* __restrict__ eidx, const int* __restrict__ eattr,
                const float* __restrict__ emb, const float* __restrict__ Wg,
                const float* __restrict__ Wv, int E)
{
    extern __shared__ float sm[];
    float4* xn4  = reinterpret_cast<float4*>(sm);
    float4* gin4 = reinterpret_cast<float4*>(sm + 16640);

    const int t  = threadIdx.x;
    const int eb = blockIdx.x * 64;

    {
        const int el = t >> 3, j = t & 7;
        const int e = eb + el;
        const int base4 = el * 65 + j * 8;
        if (e < E) {
            int s  = __ldg(eidx + e);
            int tg = __ldg(eidx + E + e);
            const float4* ps = reinterpret_cast<const float4*>(g_xs + (size_t)s  * WDIM + j * 32);
            const float4* pt = reinterpret_cast<const float4*>(g_xt + (size_t)tg * WDIM + j * 32);
            float4 xx[8];
            float sum = 0.f, sq = 0.f;
#pragma unroll
            for (int q = 0; q < 8; q++) {
                float4 a = ps[q], b = pt[q];
                float4 v = make_float4(a.x + b.x, a.y + b.y, a.z + b.z, a.w + b.w);
                xx[q] = v;
                sum += v.x + v.y + v.z + v.w;
                sq  += v.x * v.x + v.y * v.y + v.z * v.z + v.w * v.w;
            }
            float mu   = sum * (1.f / 32.f);
            float var  = sq * (1.f / 32.f) - mu * mu;
            float rstd = rsqrtf(var + 1e-5f);

            float4 bg[8];
#pragma unroll
            for (int q = 0; q < 8; q++) bg[q] = make_float4(0.f, 0.f, 0.f, 0.f);
            float cnt = 0.f;
#pragma unroll
            for (int b = 0; b < 3; b++) {
                int a = __ldg(eattr + (size_t)e * 3 + b);
                if (a != 0) {
                    cnt += 1.f;
                    const float4* pe = reinterpret_cast<const float4*>(emb + (size_t)a * WDIM + j * 32);
#pragma unroll
                    for (int q = 0; q < 8; q++) {
                        float4 ev = __ldg(pe + q);
                        bg[q].x += ev.x; bg[q].y += ev.y; bg[q].z += ev.z; bg[q].w += ev.w;
                    }
                }
            }
            float inv = 1.f / fmaxf(cnt, 1.f);
#pragma unroll
            for (int q = 0; q < 8; q++) {
                float4 xv, gv;
                xv.x = (xx[q].x - mu) * rstd;  xv.y = (xx[q].y - mu) * rstd;
                xv.z = (xx[q].z - mu) * rstd;  xv.w = (xx[q].w - mu) * rstd;
                gv.x = xv.x + bg[q].x * inv;   gv.y = xv.y + bg[q].y * inv;
                gv.z = xv.z + bg[q].z * inv;   gv.w = xv.w + bg[q].w * inv;
                xn4[base4 + q]  = xv;
                gin4[base4 + q] = gv;
            }
        } else {
            float4 z = make_float4(0.f, 0.f, 0.f, 0.f);
#pragma unroll
            for (int q = 0; q < 8; q++) { xn4[base4 + q] = z; gin4[base4 + q] = z; }
        }
    }
    __syncthreads();

    {
        const int w = t >> 5, lane = t & 31;
        const int h = w & 7, eg = w >> 3;
        u64 wgp[16], wvp[16];
        const ulonglong2* pg = reinterpret_cast<const ulonglong2*>(Wg + (size_t)(h * 32 + lane) * 32);
        const ulonglong2* pv = reinterpret_cast<const ulonglong2*>(Wv + (size_t)(h * 32 + lane) * 32);
#pragma unroll
        for (int q = 0; q < 8; q++) {
            ulonglong2 ug = __ldg(pg + q); wgp[2 * q] = ug.x; wgp[2 * q + 1] = ug.y;
            ulonglong2 uv = __ldg(pv + q); wvp[2 * q] = uv.x; wvp[2 * q + 1] = uv.y;
        }
        unsigned sxn  = (unsigned)__cvta_generic_to_shared(sm);
        unsigned sgin = sxn + 16640u * 4u;
#pragma unroll 2
        for (int i = 0; i < 32; i++) {
            int el = eg * 32 + i;
            int e  = eb + el;
            unsigned bx = sxn  + (unsigned)((el * 65 + h * 8) * 16);
            unsigned bb = sgin + (unsigned)((el * 65 + h * 8) * 16);
            u64 ga = 0ull, va = 0ull;
#pragma unroll
            for (int q = 0; q < 8; q++) {
                u64 xl, xh, gl, gh;
                lds_v2u64(gl, gh, bb + q * 16);
                lds_v2u64(xl, xh, bx + q * 16);
                ga = ffma2(gh, wgp[2 * q + 1], ffma2(gl, wgp[2 * q], ga));
                va = ffma2(xh, wvp[2 * q + 1], ffma2(xl, wvp[2 * q], va));
            }
            if (e < E) {
                float a = fmaxf(unpack_sum(ga), 0.f) * unpack_sum(va);
                __nv_bfloat16 h16 = __float2bfloat16(a);
                float lof = a - __bfloat162float(h16);
                __nv_bfloat16 l16 = __float2bfloat16(lof);
                size_t off = (size_t)e * WDIM + h * 32 + lane;
                g_act_hi[off] = *reinterpret_cast<unsigned short*>(&h16);
                g_act_lo[off] = *reinterpret_cast<unsigned short*>(&l16);
            }
        }
    }
}

// ---------------------------------------------------------------------------
// K3: HMMA (mma.sync bf16) 3-split GEMM + scatter.
// Block: 128 edges x 256 cols, K=256 in 4 chunks of 64. 512 thr = 16 warps
// (4m x 4n), warp tile 32x64. Double-buffered cp.async staging, SW128 smem.
// smem: tgt[128 int] @0, pad to 1024, then 2 stages x 98304 B
//   stage: A_hi[128x128B] | A_lo | B_hi[256x128B] | B_lo
// ---------------------------------------------------------------------------
#define STG 98304u
extern "C" __global__ void __launch_bounds__(512, 1)
gemm_scatter_kernel(const int* __restrict__ eidx, float* __restrict__ out, int E)
{
    extern __shared__ char smc[];
    unsigned sb = (unsigned)__cvta_generic_to_shared(smc);
    int* tgt_s = reinterpret_cast<int*>(smc);
    const int t = threadIdx.x, lane = t & 31, wid = t >> 5;
    const int wm = wid & 3, wn = wid >> 2;
    const int m0 = wm * 32, n0 = wn * 64;
    const int eb = blockIdx.x * 128;

    if (t < 128) {
        int e = eb + t;
        tgt_s[t] = (e < E) ? __ldg(eidx + E + e) : -1;
    }

    // ---- staging helper (c = chunk id 0..3) ----
    auto stage = [&](int c) {
        unsigned base = sb + 1024u + (unsigned)(c & 1) * STG;
        unsigned Ah = base, Al = base + 16384u, Bh = base + 32768u, Bl = base + 65536u;
        // A: 128 rows x 8 x16B ; 1024 units, 2 per thread per array
#pragma unroll
        for (int i = 0; i < 2; i++) {
            int u = t + 512 * i;
            int r = u >> 3, q = u & 7;
            unsigned off = sw128((unsigned)(r * 128 + q * 16));
            int row = eb + r;
            if (row < E) {
                const unsigned short* ph = g_act_hi + (size_t)row * 256 + c * 64 + q * 8;
                const unsigned short* pl = g_act_lo + (size_t)row * 256 + c * 64 + q * 8;
                cpa16(Ah + off, ph);
                cpa16(Al + off, pl);
            } else {
                zfill16(Ah + off);
                zfill16(Al + off);
            }
        }
        // B: 256 rows x 8 x16B ; 2048 units, 4 per thread per array
#pragma unroll
        for (int i = 0; i < 4; i++) {
            int u = t + 512 * i;
            int n = u >> 3, q = u & 7;
            unsigned off = sw128((unsigned)(n * 128 + q * 16));
            cpa16(Bh + off, g_wp_hi + (size_t)n * 256 + c * 64 + q * 8);
            cpa16(Bl + off, g_wp_lo + (size_t)n * 256 + c * 64 + q * 8);
        }
        asm volatile("cp.async.commit_group;" ::: "memory");
    };

    float acc[2][8][4];
#pragma unroll
    for (int mt = 0; mt < 2; mt++)
#pragma unroll
        for (int nn = 0; nn < 8; nn++)
#pragma unroll
            for (int q = 0; q < 4; q++) acc[mt][nn][q] = 0.f;

    stage(0);

#pragma unroll 1
    for (int c = 0; c < 4; c++) {
        if (c + 1 < 4) {
            stage(c + 1);
            asm volatile("cp.async.wait_group 1;" ::: "memory");
        } else {
            asm volatile("cp.async.wait_group 0;" ::: "memory");
        }
        __syncthreads();

        unsigned base = sb + 1024u + (unsigned)(c & 1) * STG;
        unsigned Ah = base, Al = base + 16384u, Bh = base + 32768u, Bl = base + 65536u;

#pragma unroll
        for (int ks = 0; ks < 4; ks++) {
            unsigned a_hi[2][4], a_lo[2][4];
            // A frag addresses: lane -> row m0+mt*16+(lane&15), kb = ks*32+(lane>>4)*16
#pragma unroll
            for (int mt = 0; mt < 2; mt++) {
                unsigned off = sw128((unsigned)((m0 + mt * 16 + (lane & 15)) * 128
                                                + ks * 32 + (lane >> 4) * 16));
                ldm_x4(a_hi[mt][0], a_hi[mt][1], a_hi[mt][2], a_hi[mt][3], Ah + off);
                ldm_x4(a_lo[mt][0], a_lo[mt][1], a_lo[mt][2], a_lo[mt][3], Al + off);
            }
#pragma unroll
            for (int nt = 0; nt < 4; nt++) {
                unsigned off = sw128((unsigned)((n0 + nt * 16 + (lane & 7)
                                                 + ((lane >> 4) & 1) * 8) * 128
                                                + ks * 32 + ((lane >> 3) & 1) * 16));
                unsigned bh[4], bl[4];
                ldm_x4(bh[0], bh[1], bh[2], bh[3], Bh + off);
                ldm_x4(bl[0], bl[1], bl[2], bl[3], Bl + off);
#pragma unroll
                for (int j = 0; j < 2; j++) {
                    int nn = nt * 2 + j;
                    unsigned b0h = bh[2 * j], b1h = bh[2 * j + 1];
                    unsigned b0l = bl[2 * j], b1l = bl[2 * j + 1];
#pragma unroll
                    for (int mt = 0; mt < 2; mt++) {
                        mma16816(acc[mt][nn], a_hi[mt], b0h, b1h);
                        mma16816(acc[mt][nn], a_hi[mt], b0l, b1l);
                        mma16816(acc[mt][nn], a_lo[mt], b0h, b1h);
                    }
                }
            }
        }
        __syncthreads();
    }

    // ---- epilogue: red.global.add.v2 scatter straight from fragments ----
#pragma unroll
    for (int mt = 0; mt < 2; mt++) {
        int r0 = m0 + mt * 16 + (lane >> 2);
        int r1 = r0 + 8;
        int tg0 = tgt_s[r0], tg1 = tgt_s[r1];
        float* p0 = out + (size_t)(tg0 < 0 ? 0 : tg0) * WDIM;
        float* p1 = out + (size_t)(tg1 < 0 ? 0 : tg1) * WDIM;
#pragma unroll
        for (int nn = 0; nn < 8; nn++) {
            int col = n0 + nn * 8 + (lane & 3) * 2;
            if (tg0 >= 0)
                asm volatile("red.global.add.v2.f32 [%0], {%1,%2};" ::
                             "l"(p0 + col), "f"(acc[mt][nn][0]), "f"(acc[mt][nn][1])
                             : "memory");
            if (tg1 >= 0)
                asm volatile("red.global.add.v2.f32 [%0], {%1,%2};" ::
                             "l"(p1 + col), "f"(acc[mt][nn][2]), "f"(acc[mt][nn][3])
                             : "memory");
        }
    }
}

// ---------------------------------------------------------------------------
// K4: out[n,j] *= deg[n]^deg_param[j]
// ---------------------------------------------------------------------------
extern "C" __global__ void scale_kernel(float* __restrict__ out,
                                        const float* __restrict__ deg,
                                        const float* __restrict__ dp, int N)
{
    int idx = blockIdx.x * blockDim.x + threadIdx.x;
    if (idx < N * WDIM) {
        int n = idx >> 8, j = idx & 255;
        out[idx] *= __powf(__ldg(deg + n), __ldg(dp + j));
    }
}

// ---------------------------------------------------------------------------
extern "C" void kernel_launch(void* const* d_in, const int* in_sizes, int n_in,
                              void* d_out, int out_size)
{
    const float* x    = (const float*)d_in[0];
    const float* deg  = (const float*)d_in[1];
    const int*   eidx = (const int*)d_in[2];
    const int*   eattr= (const int*)d_in[3];
    const float* Wsrc = (const float*)d_in[4];
    const float* Wtgt = (const float*)d_in[5];
    const float* emb  = (const float*)d_in[6];
    const float* Wg   = (const float*)d_in[7];
    const float* Wv   = (const float*)d_in[8];
    const float* Wp   = (const float*)d_in[9];
    const float* dp   = (const float*)d_in[10];
    float* out = (float*)d_out;

    int N = in_sizes[0] / WDIM;
    int E = in_sizes[2] / 2;

    const int NODE_SMEM = (16640 + 8192) * 4;   // 99328 B
    const int ASM_SMEM  = 16640 * 2 * 4;        // 133120 B
    const int GEMM_SMEM = 1024 + 2 * 98304;     // 197632 B

    cudaFuncSetAttribute(node_gemm_kernel,
                         cudaFuncAttributeMaxDynamicSharedMemorySize, NODE_SMEM);
    cudaFuncSetAttribute(assembly_kernel,
                         cudaFuncAttributeMaxDynamicSharedMemorySize, ASM_SMEM);
    cudaFuncSetAttribute(gemm_scatter_kernel,
                         cudaFuncAttributeMaxDynamicSharedMemorySize, GEMM_SMEM);

    cudaMemsetAsync(d_out, 0, (size_t)out_size * sizeof(float));

    wsplit_kernel<<<64, 1024>>>(Wp);
    dim3 ng((N + 63) / 64, 2);
    node_gemm_kernel<<<ng, 512, NODE_SMEM>>>(x, Wsrc, Wtgt, N);
    assembly_kernel<<<(E + 63) / 64, 512, ASM_SMEM>>>(eidx, eattr, emb, Wg, Wv, E);
    gemm_scatter_kernel<<<(E + 127) / 128, 512, GEMM_SMEM>>>(eidx, out, E);
    scale_kernel<<<((size_t)N * WDIM + 511) / 512, 512>>>(out, deg, dp, N);
}

// round 5
// speedup vs baseline: 2.6547x; 1.8865x over previous
#include <cuda_runtime.h>
#include <cuda_bf16.h>
#include <cstdint>

#define WDIM 256

// ---------------------------------------------------------------------------
// Scratch (device globals)
// ---------------------------------------------------------------------------
__device__ float g_xs[2560000];            // [N,256]
__device__ float g_xt[2560000];
__device__ unsigned short g_wp_hi[65536];  // W_post bf16 hi [n,k]
__device__ unsigned short g_wp_lo[65536];
// packed gate/val weights per chunk: [c][row=hl*32+f][ Wg d0..31 | Wv d0..31 ]
__device__ unsigned short g_wgv_hi[16384];
__device__ unsigned short g_wgv_lo[16384];

typedef unsigned long long u64;

__device__ __forceinline__ void lds_v2u64(u64 &lo, u64 &hi, unsigned addr) {
    asm volatile("ld.shared.v2.u64 {%0,%1}, [%2];" : "=l"(lo), "=l"(hi) : "r"(addr));
}
__device__ __forceinline__ u64 ffma2(u64 a, u64 b, u64 c) {
    u64 d;
    asm("fma.rn.f32x2 %0, %1, %2, %3;" : "=l"(d) : "l"(a), "l"(b), "l"(c));
    return d;
}
__device__ __forceinline__ float unpack_sum(u64 p) {
    unsigned lo, hi;
    asm("mov.b64 {%0,%1}, %2;" : "=r"(lo), "=r"(hi) : "l"(p));
    return __uint_as_float(lo) + __uint_as_float(hi);
}
__device__ __forceinline__ unsigned sw128(unsigned x) { return x ^ ((x >> 3) & 0x70u); }
__device__ __forceinline__ void cpa16(unsigned dst, const void* src) {
    asm volatile("cp.async.cg.shared.global [%0], [%1], 16;" :: "r"(dst), "l"(src));
}
__device__ __forceinline__ void ldm_x4(unsigned* r, unsigned addr) {
    asm volatile("ldmatrix.sync.aligned.m8n8.x4.shared.b16 {%0,%1,%2,%3}, [%4];"
                 : "=r"(r[0]), "=r"(r[1]), "=r"(r[2]), "=r"(r[3]) : "r"(addr));
}
__device__ __forceinline__ void mma16816(float* d, const unsigned* a,
                                         unsigned b0, unsigned b1) {
    asm volatile(
        "mma.sync.aligned.m16n8k16.row.col.f32.bf16.bf16.f32 "
        "{%0,%1,%2,%3}, {%4,%5,%6,%7}, {%8,%9}, {%0,%1,%2,%3};"
        : "+f"(d[0]), "+f"(d[1]), "+f"(d[2]), "+f"(d[3])
        : "r"(a[0]), "r"(a[1]), "r"(a[2]), "r"(a[3]), "r"(b0), "r"(b1));
}
// pack 2 fp32 -> bf16x2 (lo16 = a0)
__device__ __forceinline__ unsigned bf2(float a1, float a0) {
    unsigned d;
    asm("cvt.rn.bf16x2.f32 %0, %1, %2;" : "=r"(d) : "f"(a1), "f"(a0));
    return d;
}

// ---------------------------------------------------------------------------
// K1: node GEMM (fp32 FFMA2)
// ---------------------------------------------------------------------------
extern "C" __global__ void __launch_bounds__(512, 1)
node_gemm_kernel(const float* __restrict__ x,
                 const float* __restrict__ Wsrc,
                 const float* __restrict__ Wtgt, int N)
{
    extern __shared__ float sm[];
    float4* a4 = reinterpret_cast<float4*>(sm);
    float4* w4 = reinterpret_cast<float4*>(sm + 16640);
    const float* Wm = blockIdx.y ? Wtgt : Wsrc;
    float* og = blockIdx.y ? g_xt : g_xs;

    const int t  = threadIdx.x;
    const int nb = blockIdx.x * 64;

#pragma unroll
    for (int r = 0; r < 8; r++) {
        int id = t + 512 * r;
        int row = id >> 6, c4 = id & 63;
        int n = nb + row;
        float4 v = make_float4(0.f, 0.f, 0.f, 0.f);
        if (n < N) v = __ldg(reinterpret_cast<const float4*>(x + (size_t)n * WDIM) + c4);
        a4[row * 65 + c4] = v;
    }

    const int et = t >> 5, jt = t & 31;
    unsigned sa = (unsigned)__cvta_generic_to_shared(sm);
    unsigned sw = sa + 16640u * 4u;

    u64 accp[4][8];
#pragma unroll
    for (int ee = 0; ee < 4; ee++)
#pragma unroll
        for (int jj = 0; jj < 8; jj++) accp[ee][jj] = 0ull;

#pragma unroll 1
    for (int kt = 0; kt < 8; kt++) {
        __syncthreads();
#pragma unroll
        for (int r = 0; r < 4; r++) {
            int id = t + 512 * r;
            int j = id >> 3, kq = id & 7;
            w4[j * 8 + (kq ^ ((j >> 3) & 7))] =
                __ldg(reinterpret_cast<const float4*>(Wm + (size_t)j * WDIM + kt * 32) + kq);
        }
        __syncthreads();
#pragma unroll
        for (int kq = 0; kq < 8; kq++) {
            u64 aL[4], aH[4];
#pragma unroll
            for (int ee = 0; ee < 4; ee++)
                lds_v2u64(aL[ee], aH[ee],
                          sa + (unsigned)(((et * 4 + ee) * 65 + kt * 8 + kq) * 16));
#pragma unroll
            for (int half = 0; half < 2; half++) {
                u64 bL[4], bH[4];
#pragma unroll
                for (int jj = 0; jj < 4; jj++)
                    lds_v2u64(bL[jj], bH[jj],
                              sw + (unsigned)(((jt * 8 + half * 4 + jj) * 8 + (kq ^ (jt & 7))) * 16));
#pragma unroll
                for (int ee = 0; ee < 4; ee++)
#pragma unroll
                    for (int jj = 0; jj < 4; jj++)
                        accp[ee][half * 4 + jj] =
                            ffma2(aH[ee], bH[jj], ffma2(aL[ee], bL[jj], accp[ee][half * 4 + jj]));
            }
        }
    }

#pragma unroll
    for (int ee = 0; ee < 4; ee++) {
        int n = nb + et * 4 + ee;
        if (n >= N) continue;
        float r0 = unpack_sum(accp[ee][0]), r1 = unpack_sum(accp[ee][1]);
        float r2 = unpack_sum(accp[ee][2]), r3 = unpack_sum(accp[ee][3]);
        float r4 = unpack_sum(accp[ee][4]), r5 = unpack_sum(accp[ee][5]);
        float r6 = unpack_sum(accp[ee][6]), r7 = unpack_sum(accp[ee][7]);
        float4* py = reinterpret_cast<float4*>(og + (size_t)n * WDIM + jt * 8);
        py[0] = make_float4(r0, r1, r2, r3);
        py[1] = make_float4(r4, r5, r6, r7);
    }
}

// ---------------------------------------------------------------------------
// Weight preprocessing: W_post hi/lo split + Wg/Wv packed per-chunk hi/lo
// ---------------------------------------------------------------------------
extern "C" __global__ void wsplit_kernel(const float* __restrict__ Wp,
                                         const float* __restrict__ Wg,
                                         const float* __restrict__ Wv)
{
    int i = blockIdx.x * blockDim.x + threadIdx.x;
    if (i < 65536) {
        float v = Wp[i];
        __nv_bfloat16 h = __float2bfloat16(v);
        float lof = v - __bfloat162float(h);
        __nv_bfloat16 l = __float2bfloat16(lof);
        g_wp_hi[i] = *reinterpret_cast<unsigned short*>(&h);
        g_wp_lo[i] = *reinterpret_cast<unsigned short*>(&l);
    }
    if (i < 16384) {
        // layout: ((c*64 + row)*64 + gv*32 + d); row = hl*32 + f; h = c*2+hl
        int c   = i >> 12;
        int row = (i >> 6) & 63;
        int gv  = (i >> 5) & 1;
        int d   = i & 31;
        int h   = c * 2 + (row >> 5);
        int f   = row & 31;
        const float* Wm = gv ? Wv : Wg;
        float v = Wm[(size_t)h * 1024 + f * 32 + d];
        __nv_bfloat16 hh = __float2bfloat16(v);
        float lof = v - __bfloat162float(hh);
        __nv_bfloat16 ll = __float2bfloat16(lof);
        g_wgv_hi[i] = *reinterpret_cast<unsigned short*>(&hh);
        g_wgv_lo[i] = *reinterpret_cast<unsigned short*>(&ll);
    }
}

// ---------------------------------------------------------------------------
// K2 (fused): per 64-edge block, stream K in 4 chunks of 64 (= 2 heads):
//  P1: gather + bag + groupnorm -> xn/gin bf16 hi/lo (smem, SW128, 128B rows)
//  P2: gate/val per-head HMMA 3-split -> act = relu(g)*v -> smem bf16 hi/lo
//  P3: W_post HMMA 3-split mainloop chunk, acc in regs
//  epilogue: red.global.add.v2 scatter
// smem offsets (bytes):
//  tgt@0(256) | XNH@1024 XNL@9216 GINH@17408 GINL@25600 | ACTH@33792 ACTL@41984
//  WGVH@50176 WGVL@58368 | WPH@66560 WPL@99328 | total 132096
// ---------------------------------------------------------------------------
#define XNH_O  1024u
#define XNL_O  9216u
#define GINH_O 17408u
#define GINL_O 25600u
#define ACTH_O 33792u
#define ACTL_O 41984u
#define WGVH_O 50176u
#define WGVL_O 58368u
#define WPH_O  66560u
#define WPL_O  99328u

extern "C" __global__ void __launch_bounds__(512, 1)
fused_edge_kernel(const int* __restrict__ eidx, const int* __restrict__ eattr,
                  const float* __restrict__ emb, float* __restrict__ out, int E)
{
    extern __shared__ char smc[];
    unsigned sb = (unsigned)__cvta_generic_to_shared(smc);
    int* tgt_s = reinterpret_cast<int*>(smc);
    const int t = threadIdx.x, lane = t & 31, wid = t >> 5;
    const int eb = blockIdx.x * 64;

    if (t < 64) {
        int e = eb + t;
        tgt_s[t] = (e < E) ? __ldg(eidx + E + e) : -1;
    }
    __syncthreads();   // BUGFIX R4: tgt_s must be visible to all warps before P1

    // W_post accumulators: warp tile 32x32, 16 warps = 2m x 8n
    const int wm = wid & 1, wn = wid >> 1;
    const int m0 = wm * 32, n0 = wn * 32;
    float acc[2][4][4];
#pragma unroll
    for (int mt = 0; mt < 2; mt++)
#pragma unroll
        for (int nn = 0; nn < 4; nn++)
#pragma unroll
            for (int q = 0; q < 4; q++) acc[mt][nn][q] = 0.f;

    // P1 thread mapping
    const int e_l = t >> 3, sub = t & 7;
    const int e = eb + e_l;

    // P2 warp mapping: 16 units of (16 edges x 16 f)
    const int eg = wid >> 2, hl = (wid >> 1) & 1, nh = wid & 1;

#pragma unroll 1
    for (int c = 0; c < 4; c++) {
        // ---- stage Wp chunk (hi/lo 32KB each) + Wgv chunk (8KB each) ----
#pragma unroll
        for (int i = 0; i < 4; i++) {
            int u = t + 512 * i;
            int n = u >> 3, q = u & 7;
            unsigned off = sw128((unsigned)(n * 128 + q * 16));
            cpa16(sb + WPH_O + off, g_wp_hi + (size_t)n * 256 + c * 64 + q * 8);
            cpa16(sb + WPL_O + off, g_wp_lo + (size_t)n * 256 + c * 64 + q * 8);
        }
        {
            int r = t >> 3, q = t & 7;
            unsigned off = sw128((unsigned)(r * 128 + q * 16));
            cpa16(sb + WGVH_O + off, g_wgv_hi + (size_t)(c * 64 + r) * 64 + q * 8);
            cpa16(sb + WGVL_O + off, g_wgv_lo + (size_t)(c * 64 + r) * 64 + q * 8);
        }
        asm volatile("cp.async.commit_group;" ::: "memory");

        // ---- P1: xn/gin for this chunk's 2 heads, 8 cols per thread ----
        {
            unsigned soff = sw128((unsigned)(e_l * 128 + sub * 16));
            if (e < E) {
                int s  = __ldg(eidx + e);
                int tg = tgt_s[e_l];
                const float4* ps = reinterpret_cast<const float4*>(
                    g_xs + (size_t)s * WDIM + c * 64 + sub * 8);
                const float4* pt = reinterpret_cast<const float4*>(
                    g_xt + (size_t)tg * WDIM + c * 64 + sub * 8);
                float xx[8];
                float4 a0 = ps[0], a1 = ps[1], b0 = pt[0], b1 = pt[1];
                xx[0] = a0.x + b0.x; xx[1] = a0.y + b0.y; xx[2] = a0.z + b0.z; xx[3] = a0.w + b0.w;
                xx[4] = a1.x + b1.x; xx[5] = a1.y + b1.y; xx[6] = a1.z + b1.z; xx[7] = a1.w + b1.w;
                float sum = 0.f, sq = 0.f;
#pragma unroll
                for (int i = 0; i < 8; i++) { sum += xx[i]; sq += xx[i] * xx[i]; }
                sum += __shfl_xor_sync(0xFFFFFFFFu, sum, 1);
                sq  += __shfl_xor_sync(0xFFFFFFFFu, sq, 1);
                sum += __shfl_xor_sync(0xFFFFFFFFu, sum, 2);
                sq  += __shfl_xor_sync(0xFFFFFFFFu, sq, 2);
                float mu = sum * (1.f / 32.f);
                float var = sq * (1.f / 32.f) - mu * mu;
                float rstd = rsqrtf(var + 1e-5f);

                float bag[8];
#pragma unroll
                for (int i = 0; i < 8; i++) bag[i] = 0.f;
                float cnt = 0.f;
#pragma unroll
                for (int b = 0; b < 3; b++) {
                    int a = __ldg(eattr + (size_t)e * 3 + b);
                    if (a != 0) {
                        cnt += 1.f;
                        const float4* pe = reinterpret_cast<const float4*>(
                            emb + (size_t)a * WDIM + c * 64 + sub * 8);
                        float4 e0 = __ldg(pe), e1 = __ldg(pe + 1);
                        bag[0] += e0.x; bag[1] += e0.y; bag[2] += e0.z; bag[3] += e0.w;
                        bag[4] += e1.x; bag[5] += e1.y; bag[6] += e1.z; bag[7] += e1.w;
                    }
                }
                float inv = 1.f / fmaxf(cnt, 1.f);
                float xn[8], gn[8];
#pragma unroll
                for (int i = 0; i < 8; i++) {
                    xn[i] = (xx[i] - mu) * rstd;
                    gn[i] = xn[i] + bag[i] * inv;
                }
                unsigned xh[4], xl[4], gh[4], gl[4];
#pragma unroll
                for (int p = 0; p < 4; p++) {
                    unsigned hp = bf2(xn[2 * p + 1], xn[2 * p]);
                    float h0 = __uint_as_float(hp << 16);
                    float h1 = __uint_as_float(hp & 0xFFFF0000u);
                    xh[p] = hp;
                    xl[p] = bf2(xn[2 * p + 1] - h1, xn[2 * p] - h0);
                    hp = bf2(gn[2 * p + 1], gn[2 * p]);
                    h0 = __uint_as_float(hp << 16);
                    h1 = __uint_as_float(hp & 0xFFFF0000u);
                    gh[p] = hp;
                    gl[p] = bf2(gn[2 * p + 1] - h1, gn[2 * p] - h0);
                }
                asm volatile("st.shared.v4.b32 [%0], {%1,%2,%3,%4};" ::
                             "r"(sb + XNH_O + soff), "r"(xh[0]), "r"(xh[1]), "r"(xh[2]), "r"(xh[3]));
                asm volatile("st.shared.v4.b32 [%0], {%1,%2,%3,%4};" ::
                             "r"(sb + XNL_O + soff), "r"(xl[0]), "r"(xl[1]), "r"(xl[2]), "r"(xl[3]));
                asm volatile("st.shared.v4.b32 [%0], {%1,%2,%3,%4};" ::
                             "r"(sb + GINH_O + soff), "r"(gh[0]), "r"(gh[1]), "r"(gh[2]), "r"(gh[3]));
                asm volatile("st.shared.v4.b32 [%0], {%1,%2,%3,%4};" ::
                             "r"(sb + GINL_O + soff), "r"(gl[0]), "r"(gl[1]), "r"(gl[2]), "r"(gl[3]));
            } else {
                asm volatile("st.shared.v4.b32 [%0], {%1,%1,%1,%1};" :: "r"(sb + XNH_O + soff), "r"(0u));
                asm volatile("st.shared.v4.b32 [%0], {%1,%1,%1,%1};" :: "r"(sb + XNL_O + soff), "r"(0u));
                asm volatile("st.shared.v4.b32 [%0], {%1,%1,%1,%1};" :: "r"(sb + GINH_O + soff), "r"(0u));
                asm volatile("st.shared.v4.b32 [%0], {%1,%1,%1,%1};" :: "r"(sb + GINL_O + soff), "r"(0u));
            }
        }
        __syncthreads();
        asm volatile("cp.async.wait_group 0;" ::: "memory");
        __syncthreads();

        // ---- P2: gate/val HMMA (3-split), act -> smem ----
        {
            unsigned agh[2][4], agl[2][4], axh[2][4], axl[2][4];
            unsigned arow = (unsigned)((eg * 16 + (lane & 15)) * 128 + hl * 64 + (lane >> 4) * 16);
#pragma unroll
            for (int ks = 0; ks < 2; ks++) {
                unsigned off = sw128(arow + ks * 32);
                ldm_x4(agh[ks], sb + GINH_O + off);
                ldm_x4(agl[ks], sb + GINL_O + off);
                ldm_x4(axh[ks], sb + XNH_O + off);
                ldm_x4(axl[ks], sb + XNL_O + off);
            }
            unsigned brow = (unsigned)((hl * 32 + nh * 16 + (lane & 7) + ((lane >> 4) & 1) * 8) * 128
                                       + ((lane >> 3) & 1) * 16);
            unsigned bgh[2][4], bgl[2][4], bvh[2][4], bvl[2][4];
#pragma unroll
            for (int ks = 0; ks < 2; ks++) {
                unsigned offg = sw128(brow + ks * 32);
                unsigned offv = sw128(brow + 64 + ks * 32);
                ldm_x4(bgh[ks], sb + WGVH_O + offg);
                ldm_x4(bgl[ks], sb + WGVL_O + offg);
                ldm_x4(bvh[ks], sb + WGVH_O + offv);
                ldm_x4(bvl[ks], sb + WGVL_O + offv);
            }
            float gacc[2][4], vacc[2][4];
#pragma unroll
            for (int j = 0; j < 2; j++)
#pragma unroll
                for (int q = 0; q < 4; q++) { gacc[j][q] = 0.f; vacc[j][q] = 0.f; }
#pragma unroll
            for (int ks = 0; ks < 2; ks++)
#pragma unroll
                for (int j = 0; j < 2; j++) {
                    mma16816(gacc[j], agh[ks], bgh[ks][2 * j], bgh[ks][2 * j + 1]);
                    mma16816(gacc[j], agh[ks], bgl[ks][2 * j], bgl[ks][2 * j + 1]);
                    mma16816(gacc[j], agl[ks], bgh[ks][2 * j], bgh[ks][2 * j + 1]);
                    mma16816(vacc[j], axh[ks], bvh[ks][2 * j], bvh[ks][2 * j + 1]);
                    mma16816(vacc[j], axh[ks], bvl[ks][2 * j], bvl[ks][2 * j + 1]);
                    mma16816(vacc[j], axl[ks], bvh[ks][2 * j], bvh[ks][2 * j + 1]);
                }
            // act = relu(g)*v, split, store
#pragma unroll
            for (int j = 0; j < 2; j++)
#pragma unroll
                for (int half = 0; half < 2; half++) {
                    float a0 = fmaxf(gacc[j][half * 2], 0.f) * vacc[j][half * 2];
                    float a1 = fmaxf(gacc[j][half * 2 + 1], 0.f) * vacc[j][half * 2 + 1];
                    int row = eg * 16 + (lane >> 2) + half * 8;
                    int col = hl * 32 + nh * 16 + j * 8 + (lane & 3) * 2;
                    unsigned off = sw128((unsigned)(row * 128 + col * 2));
                    unsigned hp = bf2(a1, a0);
                    float h0 = __uint_as_float(hp << 16);
                    float h1 = __uint_as_float(hp & 0xFFFF0000u);
                    unsigned lp = bf2(a1 - h1, a0 - h0);
                    asm volatile("st.shared.b32 [%0], %1;" :: "r"(sb + ACTH_O + off), "r"(hp));
                    asm volatile("st.shared.b32 [%0], %1;" :: "r"(sb + ACTL_O + off), "r"(lp));
                }
        }
        __syncthreads();

        // ---- P3: W_post chunk mainloop (validated R3 pattern) ----
#pragma unroll
        for (int ks = 0; ks < 4; ks++) {
            unsigned ah[2][4], al[2][4];
#pragma unroll
            for (int mt = 0; mt < 2; mt++) {
                unsigned off = sw128((unsigned)((m0 + mt * 16 + (lane & 15)) * 128
                                                + ks * 32 + (lane >> 4) * 16));
                ldm_x4(ah[mt], sb + ACTH_O + off);
                ldm_x4(al[mt], sb + ACTL_O + off);
            }
#pragma unroll
            for (int nt = 0; nt < 2; nt++) {
                unsigned off = sw128((unsigned)((n0 + nt * 16 + (lane & 7)
                                                 + ((lane >> 4) & 1) * 8) * 128
                                                + ks * 32 + ((lane >> 3) & 1) * 16));
                unsigned bh[4], bl[4];
                ldm_x4(bh, sb + WPH_O + off);
                ldm_x4(bl, sb + WPL_O + off);
#pragma unroll
                for (int j = 0; j < 2; j++) {
                    int nn = nt * 2 + j;
#pragma unroll
                    for (int mt = 0; mt < 2; mt++) {
                        mma16816(acc[mt][nn], ah[mt], bh[2 * j], bh[2 * j + 1]);
                        mma16816(acc[mt][nn], ah[mt], bl[2 * j], bl[2 * j + 1]);
                        mma16816(acc[mt][nn], al[mt], bh[2 * j], bh[2 * j + 1]);
                    }
                }
            }
        }
        __syncthreads();
    }

    // ---- epilogue: scatter ----
#pragma unroll
    for (int mt = 0; mt < 2; mt++) {
        int r0 = m0 + mt * 16 + (lane >> 2);
        int r1 = r0 + 8;
        int tg0 = tgt_s[r0], tg1 = tgt_s[r1];
        float* p0 = out + (size_t)(tg0 < 0 ? 0 : tg0) * WDIM;
        float* p1 = out + (size_t)(tg1 < 0 ? 0 : tg1) * WDIM;
#pragma unroll
        for (int nn = 0; nn < 4; nn++) {
            int col = n0 + nn * 8 + (lane & 3) * 2;
            if (tg0 >= 0)
                asm volatile("red.global.add.v2.f32 [%0], {%1,%2};" ::
                             "l"(p0 + col), "f"(acc[mt][nn][0]), "f"(acc[mt][nn][1]) : "memory");
            if (tg1 >= 0)
                asm volatile("red.global.add.v2.f32 [%0], {%1,%2};" ::
                             "l"(p1 + col), "f"(acc[mt][nn][2]), "f"(acc[mt][nn][3]) : "memory");
        }
    }
}

// ---------------------------------------------------------------------------
// K3: out[n,j] *= deg[n]^deg_param[j]
// ---------------------------------------------------------------------------
extern "C" __global__ void scale_kernel(float* __restrict__ out,
                                        const float* __restrict__ deg,
                                        const float* __restrict__ dp, int N)
{
    int idx = blockIdx.x * blockDim.x + threadIdx.x;
    if (idx < N * WDIM) {
        int n = idx >> 8, j = idx & 255;
        out[idx] *= __powf(__ldg(deg + n), __ldg(dp + j));
    }
}

// ---------------------------------------------------------------------------
extern "C" void kernel_launch(void* const* d_in, const int* in_sizes, int n_in,
                              void* d_out, int out_size)
{
    const float* x    = (const float*)d_in[0];
    const float* deg  = (const float*)d_in[1];
    const int*   eidx = (const int*)d_in[2];
    const int*   eattr= (const int*)d_in[3];
    const float* Wsrc = (const float*)d_in[4];
    const float* Wtgt = (const float*)d_in[5];
    const float* emb  = (const float*)d_in[6];
    const float* Wg   = (const float*)d_in[7];
    const float* Wv   = (const float*)d_in[8];
    const float* Wp   = (const float*)d_in[9];
    const float* dp   = (const float*)d_in[10];
    float* out = (float*)d_out;

    int N = in_sizes[0] / WDIM;
    int E = in_sizes[2] / 2;

    const int NODE_SMEM  = (16640 + 8192) * 4;  // 99328 B
    const int FUSED_SMEM = 132096;

    cudaFuncSetAttribute(node_gemm_kernel,
                         cudaFuncAttributeMaxDynamicSharedMemorySize, NODE_SMEM);
    cudaFuncSetAttribute(fused_edge_kernel,
                         cudaFuncAttributeMaxDynamicSharedMemorySize, FUSED_SMEM);

    cudaMemsetAsync(d_out, 0, (size_t)out_size * sizeof(float));

    wsplit_kernel<<<64, 1024>>>(Wp, Wg, Wv);
    dim3 ng((N + 63) / 64, 2);
    node_gemm_kernel<<<ng, 512, NODE_SMEM>>>(x, Wsrc, Wtgt, N);
    fused_edge_kernel<<<(E + 63) / 64, 512, FUSED_SMEM>>>(eidx, eattr, emb, out, E);
    scale_kernel<<<((size_t)N * WDIM + 511) / 512, 512>>>(out, deg, dp, N);
}